// round 1
// baseline (speedup 1.0000x reference)
#include <cuda_runtime.h>

#define N0 1024
#define N1 512
#define I0 16
#define I1 32

// scratch (device globals: no allocation allowed)
__device__ float g_R0[N1 * N0];   // [j][a] : sum over i1 of X[j, i1, a]
__device__ float g_R1[N1 * N0];   // [j][a] : sum over i0 of X[i0, j, a]
__device__ float g_G [N1 * N0];   // [j][a] : X[j, j, a]
__device__ float g_S [N0];        // sum_j R0[j][a]
__device__ float g_D [N0];        // sum_j G[j][a]
__device__ float g_Rh0[N1];       // sum_a R0[j][a]
__device__ float g_Rh1[N1];       // sum_a R1[j][a]
__device__ float g_Gh [N1];       // sum_a G[j][a]
__device__ float g_scal[2];       // { sum_a S, sum_a D }

__device__ __forceinline__ void red4(float* addr, float4 v) {
    asm volatile("red.global.add.v4.f32 [%0], {%1, %2, %3, %4};"
                 :: "l"(addr), "f"(v.x), "f"(v.y), "f"(v.z), "f"(v.w)
                 : "memory");
}

__global__ void zero_kernel() {
    int i = blockIdx.x * blockDim.x + threadIdx.x;
    float4 z = make_float4(0.f, 0.f, 0.f, 0.f);
    if (i < (N1 * N0) / 4) {
        reinterpret_cast<float4*>(g_R0)[i] = z;
        reinterpret_cast<float4*>(g_R1)[i] = z;
    }
    if (i < N0 / 4) {
        reinterpret_cast<float4*>(g_S)[i] = z;
        reinterpret_cast<float4*>(g_D)[i] = z;
    }
}

// Single streaming pass over X (1 GiB). Each block: 16 i0 x 32 i1 x full a.
// R0 accumulated fully over the block's i1 range in registers (64 regs),
// R1 accumulated over the block's i0 range per i1, then one v4 red each.
__global__ __launch_bounds__(256, 2) void main_pass(const float* __restrict__ X) {
    const int i0base = blockIdx.x * I0;   // 32 groups
    const int i1base = blockIdx.y * I1;   // 16 groups
    const int tx = threadIdx.x;           // float4 lane within the a-row (0..255)
    const float4* __restrict__ Xv = reinterpret_cast<const float4*>(X);

    float4 r0acc[I0];
    #pragma unroll
    for (int k = 0; k < I0; k++) r0acc[k] = make_float4(0.f, 0.f, 0.f, 0.f);

    for (int t = 0; t < I1; t++) {
        const int i1 = i1base + t;
        float4 r1 = make_float4(0.f, 0.f, 0.f, 0.f);
        #pragma unroll
        for (int k = 0; k < I0; k++) {
            const float4 v = __ldcs(Xv + (size_t)((i0base + k) * N1 + i1) * (N0 / 4) + tx);
            r0acc[k].x += v.x; r0acc[k].y += v.y; r0acc[k].z += v.z; r0acc[k].w += v.w;
            r1.x += v.x; r1.y += v.y; r1.z += v.z; r1.w += v.w;
        }
        red4(&g_R1[(size_t)i1 * N0 + tx * 4], r1);
    }
    #pragma unroll
    for (int k = 0; k < I0; k++)
        red4(&g_R0[(size_t)(i0base + k) * N0 + tx * 4], r0acc[k]);
}

// Per-j reductions over a, plus diagonal gather; also scatter into S[a], D[a].
__global__ void reduce_j(const float* __restrict__ X) {
    const int j  = blockIdx.x;    // 0..511
    const int tx = threadIdx.x;   // 0..255 (float4 lanes over a)

    const float4 r0 = reinterpret_cast<const float4*>(g_R0)[j * (N0 / 4) + tx];
    const float4 r1 = reinterpret_cast<const float4*>(g_R1)[j * (N0 / 4) + tx];
    const float4 g  = __ldg(reinterpret_cast<const float4*>(X) +
                            (size_t)(j * N1 + j) * (N0 / 4) + tx);
    reinterpret_cast<float4*>(g_G)[j * (N0 / 4) + tx] = g;

    red4(&g_S[tx * 4], r0);
    red4(&g_D[tx * 4], g);

    float s0 = r0.x + r0.y + r0.z + r0.w;
    float s1 = r1.x + r1.y + r1.z + r1.w;
    float sg = g.x  + g.y  + g.z  + g.w;

    #pragma unroll
    for (int o = 16; o > 0; o >>= 1) {
        s0 += __shfl_down_sync(0xffffffffu, s0, o);
        s1 += __shfl_down_sync(0xffffffffu, s1, o);
        sg += __shfl_down_sync(0xffffffffu, sg, o);
    }
    __shared__ float sm[3][8];
    const int lane = tx & 31, w = tx >> 5;
    if (lane == 0) { sm[0][w] = s0; sm[1][w] = s1; sm[2][w] = sg; }
    __syncthreads();
    if (tx == 0) {
        float a0 = 0.f, a1 = 0.f, ag = 0.f;
        #pragma unroll
        for (int i = 0; i < 8; i++) { a0 += sm[0][i]; a1 += sm[1][i]; ag += sm[2][i]; }
        g_Rh0[j] = a0; g_Rh1[j] = a1; g_Gh[j] = ag;
    }
}

__global__ void scal_kernel() {
    const int tx = threadIdx.x;   // 256 threads, N0/4 = 256 float4s
    const float4 s = reinterpret_cast<const float4*>(g_S)[tx];
    const float4 d = reinterpret_cast<const float4*>(g_D)[tx];
    float ss = s.x + s.y + s.z + s.w;
    float dd = d.x + d.y + d.z + d.w;
    #pragma unroll
    for (int o = 16; o > 0; o >>= 1) {
        ss += __shfl_down_sync(0xffffffffu, ss, o);
        dd += __shfl_down_sync(0xffffffffu, dd, o);
    }
    __shared__ float sm[2][8];
    const int lane = tx & 31, w = tx >> 5;
    if (lane == 0) { sm[0][w] = ss; sm[1][w] = dd; }
    __syncthreads();
    if (tx == 0) {
        float a0 = 0.f, a1 = 0.f;
        #pragma unroll
        for (int i = 0; i < 8; i++) { a0 += sm[0][i]; a1 += sm[1][i]; }
        g_scal[0] = a0; g_scal[1] = a1;
    }
}

// Transposing finalize: scratch is [j][a], output is Y[a][j].
// 32x32 tiles through smem for coalesced loads AND stores.
__global__ void finalize(const float* __restrict__ w, float* __restrict__ Y) {
    __shared__ float t0[32][33], t1[32][33], tg[32][33];
    const int at = blockIdx.x * 32;   // a tile (32 tiles)
    const int jt = blockIdx.y * 32;   // j tile (16 tiles)
    const int tx = threadIdx.x;       // 0..31
    const int ty = threadIdx.y;       // 0..7

    #pragma unroll
    for (int r = 0; r < 4; r++) {
        const int jl = ty + r * 8;
        t0[jl][tx] = g_R0[(size_t)(jt + jl) * N0 + at + tx];
        t1[jl][tx] = g_R1[(size_t)(jt + jl) * N0 + at + tx];
        tg[jl][tx] = g_G [(size_t)(jt + jl) * N0 + at + tx];
    }
    __syncthreads();

    const float w0 = w[0], w1 = w[1], w2 = w[2], w3 = w[3], w4 = w[4];
    const float w5 = w[5], w6 = w[6], w7 = w[7], w8 = w[8], w9 = w[9];
    const float c  = w5 * g_scal[0] + w6 * g_scal[1];
    const int   j  = jt + tx;
    const float cj = c + w7 * g_Rh0[j] + w8 * g_Rh1[j] + w9 * g_Gh[j];

    #pragma unroll
    for (int r = 0; r < 4; r++) {
        const int al = ty + r * 8;
        const int a  = at + al;
        const float val = cj + w0 * g_S[a] + w1 * g_D[a]
                        + w2 * t0[tx][al] + w3 * t1[tx][al] + w4 * tg[tx][al];
        Y[(size_t)a * N1 + j] = val;
    }
}

extern "C" void kernel_launch(void* const* d_in, const int* in_sizes, int n_in,
                              void* d_out, int out_size) {
    const float* X = (const float*)d_in[0];   // (512, 512, 1024) fp32
    const float* w = (const float*)d_in[1];   // (10, 1, 1) fp32
    float* Y = (float*)d_out;                 // (1024, 512) fp32

    zero_kernel<<<(N1 * N0 / 4 + 255) / 256, 256>>>();
    main_pass<<<dim3(N1 / I0, N1 / I1), 256>>>(X);
    reduce_j<<<N1, 256>>>(X);
    scal_kernel<<<1, 256>>>();
    finalize<<<dim3(N0 / 32, N1 / 32), dim3(32, 8)>>>(w, Y);
}

// round 2
// speedup vs baseline: 1.0240x; 1.0240x over previous
#include <cuda_runtime.h>

#define N0 1024
#define N1 512
#define I0 16
#define I1 32

// scratch (device globals: no allocation allowed)
__device__ float g_R0[N1 * N0];   // [j][a] : sum over i1 of X[j, i1, a]
__device__ float g_R1[N1 * N0];   // [j][a] : sum over i0 of X[i0, j, a]
__device__ float g_G [N1 * N0];   // [j][a] : X[j, j, a]
__device__ float g_S [N0];        // sum_j R0[j][a]
__device__ float g_D [N0];        // sum_j G[j][a]
__device__ float g_Rh0[N1];       // sum_a R0[j][a]
__device__ float g_Rh1[N1];       // sum_a R1[j][a]
__device__ float g_Gh [N1];       // sum_a G[j][a]
__device__ float g_scal[2];       // { sum_a S, sum_a D }

__device__ __forceinline__ void red4(float* addr, float4 v) {
    asm volatile("red.global.add.v4.f32 [%0], {%1, %2, %3, %4};"
                 :: "l"(addr), "f"(v.x), "f"(v.y), "f"(v.z), "f"(v.w)
                 : "memory");
}

__global__ void zero_kernel() {
    int i = blockIdx.x * blockDim.x + threadIdx.x;
    float4 z = make_float4(0.f, 0.f, 0.f, 0.f);
    if (i < (N1 * N0) / 4) {
        reinterpret_cast<float4*>(g_R0)[i] = z;
        reinterpret_cast<float4*>(g_R1)[i] = z;
    }
    if (i < N0 / 4) {
        reinterpret_cast<float4*>(g_S)[i] = z;
        reinterpret_cast<float4*>(g_D)[i] = z;
    }
    if (i == 0) { g_scal[0] = 0.f; g_scal[1] = 0.f; }
}

// Single streaming pass over X (1 GiB). Each block: 16 i0 x 32 i1 x half the
// a-range (128 float4 lanes). R0 accumulated fully over the block's i1 range
// in registers (64 regs), R1 accumulated over the block's i0 range per i1,
// then one v4 red each. 1024 blocks x 1 MB reads -> fine-grained stealing.
__global__ __launch_bounds__(128, 4) void main_pass(const float* __restrict__ X) {
    const int i0base = blockIdx.x * I0;                 // 32 groups
    const int i1base = blockIdx.y * I1;                 // 16 groups
    const int ax = blockIdx.z * 128 + threadIdx.x;      // float4 lane (0..255)
    const float4* __restrict__ Xv = reinterpret_cast<const float4*>(X);

    float4 r0acc[I0];
    #pragma unroll
    for (int k = 0; k < I0; k++) r0acc[k] = make_float4(0.f, 0.f, 0.f, 0.f);

    for (int t = 0; t < I1; t++) {
        const int i1 = i1base + t;
        float4 r1 = make_float4(0.f, 0.f, 0.f, 0.f);
        #pragma unroll
        for (int k = 0; k < I0; k++) {
            const float4 v = __ldcs(Xv + (size_t)((i0base + k) * N1 + i1) * (N0 / 4) + ax);
            r0acc[k].x += v.x; r0acc[k].y += v.y; r0acc[k].z += v.z; r0acc[k].w += v.w;
            r1.x += v.x; r1.y += v.y; r1.z += v.z; r1.w += v.w;
        }
        red4(&g_R1[(size_t)i1 * N0 + ax * 4], r1);
    }
    #pragma unroll
    for (int k = 0; k < I0; k++)
        red4(&g_R0[(size_t)(i0base + k) * N0 + ax * 4], r0acc[k]);
}

// Per-j reductions over a, diagonal gather, S[a]/D[a] scatter, and the two
// global scalars (sum_a S = sum_j Rh0[j], sum_a D = sum_j Gh[j]) via atomics.
__global__ void reduce_j(const float* __restrict__ X) {
    const int j  = blockIdx.x;    // 0..511
    const int tx = threadIdx.x;   // 0..255 (float4 lanes over a)

    const float4 r0 = reinterpret_cast<const float4*>(g_R0)[j * (N0 / 4) + tx];
    const float4 r1 = reinterpret_cast<const float4*>(g_R1)[j * (N0 / 4) + tx];
    const float4 g  = __ldg(reinterpret_cast<const float4*>(X) +
                            (size_t)(j * N1 + j) * (N0 / 4) + tx);
    reinterpret_cast<float4*>(g_G)[j * (N0 / 4) + tx] = g;

    red4(&g_S[tx * 4], r0);
    red4(&g_D[tx * 4], g);

    float s0 = r0.x + r0.y + r0.z + r0.w;
    float s1 = r1.x + r1.y + r1.z + r1.w;
    float sg = g.x  + g.y  + g.z  + g.w;

    #pragma unroll
    for (int o = 16; o > 0; o >>= 1) {
        s0 += __shfl_down_sync(0xffffffffu, s0, o);
        s1 += __shfl_down_sync(0xffffffffu, s1, o);
        sg += __shfl_down_sync(0xffffffffu, sg, o);
    }
    __shared__ float sm[3][8];
    const int lane = tx & 31, w = tx >> 5;
    if (lane == 0) { sm[0][w] = s0; sm[1][w] = s1; sm[2][w] = sg; }
    __syncthreads();
    if (tx == 0) {
        float a0 = 0.f, a1 = 0.f, ag = 0.f;
        #pragma unroll
        for (int i = 0; i < 8; i++) { a0 += sm[0][i]; a1 += sm[1][i]; ag += sm[2][i]; }
        g_Rh0[j] = a0; g_Rh1[j] = a1; g_Gh[j] = ag;
        atomicAdd(&g_scal[0], a0);   // sum_a S
        atomicAdd(&g_scal[1], ag);   // sum_a D
    }
}

// Transposing finalize: scratch is [j][a], output is Y[a][j].
// 32x32 tiles through smem for coalesced loads AND stores.
__global__ void finalize(const float* __restrict__ w, float* __restrict__ Y) {
    __shared__ float t0[32][33], t1[32][33], tg[32][33];
    const int at = blockIdx.x * 32;   // a tile (32 tiles)
    const int jt = blockIdx.y * 32;   // j tile (16 tiles)
    const int tx = threadIdx.x;       // 0..31
    const int ty = threadIdx.y;       // 0..7

    #pragma unroll
    for (int r = 0; r < 4; r++) {
        const int jl = ty + r * 8;
        t0[jl][tx] = g_R0[(size_t)(jt + jl) * N0 + at + tx];
        t1[jl][tx] = g_R1[(size_t)(jt + jl) * N0 + at + tx];
        tg[jl][tx] = g_G [(size_t)(jt + jl) * N0 + at + tx];
    }
    __syncthreads();

    const float w0 = w[0], w1 = w[1], w2 = w[2], w3 = w[3], w4 = w[4];
    const float w5 = w[5], w6 = w[6], w7 = w[7], w8 = w[8], w9 = w[9];
    const float c  = w5 * g_scal[0] + w6 * g_scal[1];
    const int   j  = jt + tx;
    const float cj = c + w7 * g_Rh0[j] + w8 * g_Rh1[j] + w9 * g_Gh[j];

    #pragma unroll
    for (int r = 0; r < 4; r++) {
        const int al = ty + r * 8;
        const int a  = at + al;
        const float val = cj + w0 * g_S[a] + w1 * g_D[a]
                        + w2 * t0[tx][al] + w3 * t1[tx][al] + w4 * tg[tx][al];
        Y[(size_t)a * N1 + j] = val;
    }
}

extern "C" void kernel_launch(void* const* d_in, const int* in_sizes, int n_in,
                              void* d_out, int out_size) {
    const float* X = (const float*)d_in[0];   // (512, 512, 1024) fp32
    const float* w = (const float*)d_in[1];   // (10, 1, 1) fp32
    float* Y = (float*)d_out;                 // (1024, 512) fp32

    zero_kernel<<<(N1 * N0 / 4 + 255) / 256, 256>>>();
    main_pass<<<dim3(N1 / I0, N1 / I1, 2), 128>>>(X);
    reduce_j<<<N1, 256>>>(X);
    finalize<<<dim3(N0 / 32, N1 / 32), dim3(32, 8)>>>(w, Y);
}